// round 13
// baseline (speedup 1.0000x reference)
#include <cuda_runtime.h>
#include <cuda_fp16.h>

#define NBLK 256
#define NTHR 256
#define T_STEPS 512
#define PLEN 64

#define BK 128                // k-halves per stage
#define RING 3
#define LA 2
#define SA 136                // smem row stride in halves (BK + 8)
#define ASTAGE (64 * SA)      // halves
#define BSTAGE (32 * SA)      // halves
#define NKS 4                 // k-split warps within CTA
#define WFC_OFF (RING * (ASTAGE + BSTAGE))     // halves; gates alias ring base
#define SMEM_BYTES ((WFC_OFF + 4 * 1024) * 2)

#define S0 9                  // layer0 global stages: 8 H + 1 X (K=1152)
#define S12 16                // layers 1/2: 8 H + 8 X (K=2048)
#define L0SZ (128 * S0 * 4096)
#define L12SZ (128 * S12 * 4096)

// ---------------- device state ----------------
__device__ __half g_Wp0[L0SZ];
__device__ __half g_Wp1[L12SZ];
__device__ __half g_Wp2[L12SZ];
__device__ __half g_Wfch[128 * 1024];
__device__ float  g_bsum[3 * 4096];
__device__ __half g_In0[64 * 128];
__device__ __half g_X1[64 * 1024];
__device__ __half g_X2[64 * 1024];
__device__ __half g_Xfc[64 * 1024];
__device__ __half g_Hst[3][2][64 * 1024];
__device__ float  g_Cst[3 * 64 * 1024];
__device__ float  g_Gpart[128 * 2 * 2048];   // per-pair double-buffered gate partials
__device__ unsigned g_flag[128];             // per-pair monotonic flags
__device__ unsigned g_cnt[2];                // parity-indexed arrival counters
__device__ unsigned g_gen;                   // completed-barrier count

// ---------------- helpers ----------------
__device__ __forceinline__ float sigf(float v) { return 1.0f / (1.0f + expf(-v)); }

__device__ __forceinline__ unsigned smaddr(const void* p) {
    return (unsigned)__cvta_generic_to_shared(p);
}
__device__ __forceinline__ void cp16(unsigned dst, const void* src) {
    asm volatile("cp.async.cg.shared.global [%0], [%1], 16;" :: "r"(dst), "l"(src));
}
__device__ __forceinline__ void cp_commit() { asm volatile("cp.async.commit_group;"); }

__device__ __forceinline__ void ldsm4(unsigned& r0, unsigned& r1, unsigned& r2, unsigned& r3,
                                      unsigned addr) {
    asm volatile("ldmatrix.sync.aligned.m8n8.x4.shared.b16 {%0,%1,%2,%3}, [%4];"
                 : "=r"(r0), "=r"(r1), "=r"(r2), "=r"(r3) : "r"(addr));
}
__device__ __forceinline__ void mma16816(float c[4],
    unsigned a0, unsigned a1, unsigned a2, unsigned a3, unsigned b0, unsigned b1) {
    asm volatile("mma.sync.aligned.m16n8k16.row.col.f32.f16.f16.f32 "
        "{%0,%1,%2,%3}, {%4,%5,%6,%7}, {%8,%9}, {%0,%1,%2,%3};"
        : "+f"(c[0]), "+f"(c[1]), "+f"(c[2]), "+f"(c[3])
        : "r"(a0), "r"(a1), "r"(a2), "r"(a3), "r"(b0), "r"(b1));
}

// ---- parity-slot grid barrier: deadlock-free with <=1-barrier run-ahead ----
__device__ __forceinline__ void bar_arrive(int tid, int par) {
    __syncthreads();
    if (tid == 0) {
        unsigned arr;
        asm volatile("atom.release.gpu.global.add.u32 %0, [%1], %2;"
                     : "=r"(arr) : "l"(&g_cnt[par]), "r"(1u));
        if (arr == NBLK - 1) {
            *(volatile unsigned*)&g_cnt[par] = 0;
            asm volatile("red.release.gpu.global.add.u32 [%0], %1;" :: "l"(&g_gen), "r"(1u));
        }
    }
}
__device__ __forceinline__ void bar_wait(int tid, unsigned target) {
    if (tid == 0) {
        unsigned cur;
        do {
            asm volatile("ld.acquire.gpu.global.u32 %0, [%1];" : "=r"(cur) : "l"(&g_gen));
        } while ((int)(cur - target) < 0);
    }
    __syncthreads();
}

// ---------------- packing / init ----------------
// Wp[((cg*S + s)*32 + col)*128 + kk]; col = gate*8 + nl; H-part first
// (s<8 -> Whh k=s*128+kk; s>=8 -> Wih); row = gate*1024 + cg*8 + nl.
__global__ void pack_all(const float* __restrict__ Wih0, const float* __restrict__ Whh0,
                         const float* __restrict__ Wih1, const float* __restrict__ Whh1,
                         const float* __restrict__ Wih2, const float* __restrict__ Whh2) {
    int idx = blockIdx.x * blockDim.x + threadIdx.x;
    const float *Wih, *Whh;
    __half* Wp;
    int S, Kin, i = idx;
    if (i < L0SZ)               { Wp = g_Wp0; S = S0;  Kin = 128;  Wih = Wih0; Whh = Whh0; }
    else if (i < L0SZ + L12SZ)  { i -= L0SZ;  Wp = g_Wp1; S = S12; Kin = 1024; Wih = Wih1; Whh = Whh1; }
    else if (i < L0SZ + 2*L12SZ){ i -= L0SZ + L12SZ; Wp = g_Wp2; S = S12; Kin = 1024; Wih = Wih2; Whh = Whh2; }
    else return;
    int kk   = i & 127;
    int col  = (i >> 7) & 31;
    int rest = i >> 12;
    int s    = rest % S;
    int cg   = rest / S;
    int row  = ((col >> 3) << 10) + cg * 8 + (col & 7);
    float v  = (s < 8) ? Whh[row * 1024 + s * 128 + kk]
                       : Wih[row * Kin + (s - 8) * 128 + kk];
    Wp[i] = __float2half(v);
}

__global__ void pack_fc(const float* __restrict__ Wfc) {
    int i = blockIdx.x * blockDim.x + threadIdx.x;
    if (i < 128 * 1024) g_Wfch[i] = __float2half(Wfc[i]);
}

__global__ void init_state(const float* __restrict__ x, const float* __restrict__ h0,
                           const float* __restrict__ c0,
                           const float* __restrict__ bih0, const float* __restrict__ bhh0,
                           const float* __restrict__ bih1, const float* __restrict__ bhh1,
                           const float* __restrict__ bih2, const float* __restrict__ bhh2,
                           float* __restrict__ out) {
    int i = blockIdx.x * blockDim.x + threadIdx.x;
    if (i == 0) { g_gen = 0; g_cnt[0] = 0; g_cnt[1] = 0; }
    if (i < 128) g_flag[i] = 0;
    if (i < 8192) { float v = x[i]; g_In0[i] = __float2half(v); out[i] = v; }
    if (i < 3 * 65536) {
        g_Hst[i >> 16][0][i & 65535] = __float2half(h0[i]);
        g_Cst[i] = c0[i];
    }
    if (i < 4096) {
        g_bsum[i]        = bih0[i] + bhh0[i];
        g_bsum[4096 + i] = bih1[i] + bhh1[i];
        g_bsum[8192 + i] = bih2[i] + bhh2[i];
    }
}

// ---------------- main persistent kernel ----------------
extern __shared__ __half sm_raw[];

struct Ctx {
    int tid, p, kh;
    unsigned AsBase, BsBase;
    unsigned aOff, bOff;       // per-lane ldmatrix offsets (bytes)
    int mh, ks;                // warp mapping: m-half (32 rows), k-chunk (32 halves)
};

__device__ __forceinline__ void load_stage(const Ctx& cx,
    const __half* __restrict__ Hp, const __half* __restrict__ Xin, int ldX,
    const __half* __restrict__ wseg, int sg, int slot)
{
    unsigned adst = cx.AsBase + (unsigned)(slot * ASTAGE) * 2u;
    unsigned bdst = cx.BsBase + (unsigned)(slot * BSTAGE) * 2u;
    const __half* a; int ld;
    if (sg < 8) { a = Hp + sg * BK; ld = 1024; }
    else        { a = Xin + (sg - 8) * BK; ld = ldX; }
#pragma unroll
    for (int i = 0; i < 4; ++i) {
        int q = cx.tid + i * 256;
        int ar = q >> 4, au = q & 15;
        cp16(adst + (unsigned)(ar * SA + au * 8) * 2u, a + ar * ld + au * 8);
    }
    const __half* w = wseg + (size_t)sg * 4096;
#pragma unroll
    for (int i = 0; i < 2; ++i) {
        int q = cx.tid + i * 256;
        int bcid = q >> 4, bu = q & 15;
        cp16(bdst + (unsigned)(bcid * SA + bu * 8) * 2u, w + bcid * 128 + bu * 8);
    }
}

// runs this CTA's K-half: stages (kh*4 .. kh*4+3 = H) then X stages at sxoff..
__device__ __forceinline__ void gemm_kh(const Ctx& cx, int nloc, int sxoff,
    const __half* __restrict__ Hp, const __half* __restrict__ Xin, int ldX,
    const __half* __restrict__ wseg, unsigned wtarget, bool xw)
{
    float acc[2][2][2][4];
#pragma unroll
    for (int a = 0; a < 2; ++a)
#pragma unroll
        for (int b = 0; b < 2; ++b)
#pragma unroll
            for (int c = 0; c < 2; ++c)
#pragma unroll
                for (int d = 0; d < 4; ++d) acc[a][b][c][d] = 0.f;

#pragma unroll
    for (int i = 0; i < LA; ++i) {                 // H-stage prologue (barrier-free)
        load_stage(cx, Hp, Xin, ldX, wseg, cx.kh * 4 + i, i);
        cp_commit();
    }

#pragma unroll 1
    for (int s = 0; s < nloc; ++s) {
        asm volatile("cp.async.wait_group %0;" :: "n"(LA - 1));
        __syncthreads();
        int u = s + LA;
        if (u < nloc) {
            if (xw && u == 4) bar_wait(cx.tid, wtarget);     // X inputs published
            int sg = (u < 4) ? cx.kh * 4 + u : sxoff + (u - 4);
            load_stage(cx, Hp, Xin, ldX, wseg, sg, u % RING);
        }
        cp_commit();

        int slot = s % RING;
        unsigned aBase = cx.AsBase + (unsigned)(slot * ASTAGE) * 2u + cx.aOff;
        unsigned bBase = cx.BsBase + (unsigned)(slot * BSTAGE) * 2u + cx.bOff;
#pragma unroll
        for (int kk = 0; kk < 2; ++kk) {
            unsigned b0[4], b1[4];
            ldsm4(b0[0], b0[1], b0[2], b0[3], bBase + kk * 32u);
            ldsm4(b1[0], b1[1], b1[2], b1[3], bBase + 16u * SA * 2u + kk * 32u);
#pragma unroll
            for (int mt = 0; mt < 2; ++mt) {
                unsigned a0, a1, a2, a3;
                ldsm4(a0, a1, a2, a3, aBase + mt * (16u * SA * 2u) + kk * 32u);
                mma16816(acc[mt][0][0], a0, a1, a2, a3, b0[0], b0[1]);
                mma16816(acc[mt][0][1], a0, a1, a2, a3, b0[2], b0[3]);
                mma16816(acc[mt][1][0], a0, a1, a2, a3, b1[0], b1[1]);
                mma16816(acc[mt][1][1], a0, a1, a2, a3, b1[2], b1[3]);
            }
        }
    }
    __syncthreads();      // gates region aliases ring: all compute done first

    // store partial gates (per k-chunk buffer), 4 bufs of 64x33 f32 at ring base
    {
        const int lane = cx.tid & 31;
        float* gk = (float*)sm_raw + cx.ks * (64 * 33);
        int r = lane >> 2, p2 = (lane & 3) * 2;
#pragma unroll
        for (int mt = 0; mt < 2; ++mt)
#pragma unroll
            for (int hb = 0; hb < 2; ++hb)
#pragma unroll
                for (int n8 = 0; n8 < 2; ++n8) {
                    int row = cx.mh * 32 + mt * 16 + r;
                    int col = hb * 16 + n8 * 8 + p2;
                    float* q = acc[mt][hb][n8];
                    gk[row * 33 + col]           = q[0];
                    gk[row * 33 + col + 1]       = q[1];
                    gk[(row + 8) * 33 + col]     = q[2];
                    gk[(row + 8) * 33 + col + 1] = q[3];
                }
    }
    __syncthreads();
}

// kh1: export summed partials to L2 and release the pair flag
__device__ __forceinline__ void epi_kh1(const Ctx& cx, int L) {
    const float* gates = (const float*)sm_raw;
    float* Gp = g_Gpart + ((size_t)cx.p * 2 + (L & 1)) * 2048;
#pragma unroll
    for (int j = 0; j < 8; ++j) {
        int i = cx.tid + j * 256;
        int e = (i >> 5) * 33 + (i & 31);
        float v = gates[e] + gates[64 * 33 + e] + gates[2 * 64 * 33 + e]
                + gates[3 * 64 * 33 + e];
        __stcg(Gp + i, v);
    }
    __threadfence();
    __syncthreads();
    if (cx.tid == 0)
        asm volatile("red.release.gpu.global.add.u32 [%0], %1;"
                     :: "l"(g_flag + cx.p), "r"(1u));
}

// kh0: wait for partner partials, fuse full LSTM cell
__device__ __forceinline__ void epi_kh0(const Ctx& cx, int L,
    const float* __restrict__ bsumL, float* __restrict__ Cl,
    __half* __restrict__ Hn, __half* __restrict__ Xn)
{
    if (cx.tid == 0) {
        unsigned cur, target = (unsigned)(L + 1);
        do {
            asm volatile("ld.acquire.gpu.global.u32 %0, [%1];"
                         : "=r"(cur) : "l"(g_flag + cx.p));
        } while ((int)(cur - target) < 0);
    }
    __syncthreads();
    const float* gates = (const float*)sm_raw;
    const float* Gp = g_Gpart + ((size_t)cx.p * 2 + (L & 1)) * 2048;
#pragma unroll
    for (int k = 0; k < 2; ++k) {
        int item = cx.tid + k * 256;
        int b = item >> 3, nl = item & 7;
        int ng = cx.p * 8 + nl;
        int e = b * 33 + nl;
        float gi = 0.f, gf = 0.f, gg = 0.f, go = 0.f;
#pragma unroll
        for (int kb = 0; kb < NKS; ++kb) {
            const float* g = gates + kb * (64 * 33);
            gi += g[e];
            gf += g[e + 8];
            gg += g[e + 16];
            go += g[e + 24];
        }
        gi += __ldcg(Gp + b * 32 + nl);
        gf += __ldcg(Gp + b * 32 + 8 + nl);
        gg += __ldcg(Gp + b * 32 + 16 + nl);
        go += __ldcg(Gp + b * 32 + 24 + nl);
        gi += bsumL[ng]; gf += bsumL[1024 + ng];
        gg += bsumL[2048 + ng]; go += bsumL[3072 + ng];
        float c  = Cl[b * 1024 + ng];
        float cn = sigf(gf) * c + sigf(gi) * tanhf(gg);
        float h  = sigf(go) * tanhf(cn);
        Cl[b * 1024 + ng] = cn;
        __half hh = __float2half(h);
        Hn[b * 1024 + ng] = hh;
        Xn[b * 1024 + ng] = hh;
    }
}

__global__ void __launch_bounds__(NTHR, 2)
lstm_main(const float* __restrict__ x, const float* __restrict__ bfc,
          float* __restrict__ out)
{
    const int tid = threadIdx.x, bc = blockIdx.x;
    Ctx cx;
    cx.tid = tid;
    cx.p = bc >> 1;                    // pair = col-group 0..127
    cx.kh = bc & 1;                    // K-half
    cx.AsBase = smaddr(sm_raw);
    cx.BsBase = smaddr(sm_raw + RING * ASTAGE);
    {
        const int lane = tid & 31, wid = tid >> 5;
        cx.mh = wid & 1;               // m-half (32 rows)
        cx.ks = wid >> 1;              // k-chunk 0..3 (32 halves each)
        int aRow = cx.mh * 32 + ((lane >> 3) & 1) * 8 + (lane & 7);
        cx.aOff = (unsigned)(aRow * SA + (lane >> 4) * 8 + cx.ks * 32) * 2u;
        int bRow = ((lane >> 4) & 1) * 8 + (lane & 7);
        cx.bOff = (unsigned)(bRow * SA + ((lane >> 3) & 1) * 8 + cx.ks * 32) * 2u;
    }
    __half* sWfc = sm_raw + WFC_OFF;

    // cache this CTA's fc weight slice (4 rows x 1024 halves)
    {
        const int cg2 = bc & 31;
        const __half* src = g_Wfch + cg2 * 4 * 1024;
#pragma unroll
        for (int i = 0; i < 2; ++i) {
            int e = (tid + i * 256) * 8;
            cp16(smaddr(sWfc + e), src + e);
        }
        cp_commit();
        asm volatile("cp.async.wait_group 0;");
        __syncthreads();
    }

    const __half* Wb0 = g_Wp0 + (size_t)cx.p * S0 * 4096;
    const __half* Wb1 = g_Wp1 + (size_t)cx.p * S12 * 4096;
    const __half* Wb2 = g_Wp2 + (size_t)cx.p * S12 * 4096;
    const int nloc0 = (cx.kh == 0) ? 5 : 4;
    const int sx12 = 8 + cx.kh * 4;

#pragma unroll 1
    for (int t = 0; t < T_STEPS - 1; ++t) {
        int p = t & 1;
        unsigned b4 = (unsigned)(t * 4);
        int L = t * 3;

        // L0: kh0 owns the X stage (needs In0, gen b4)
        gemm_kh(cx, nloc0, 8, g_Hst[0][p], g_In0, 128, Wb0, b4, cx.kh == 0);
        if (cx.kh == 0) epi_kh0(cx, L, g_bsum, g_Cst, g_Hst[0][p ^ 1], g_X1);
        else            epi_kh1(cx, L);
        bar_arrive(tid, 0);                            // barrier 4t   -> gen b4+1

        gemm_kh(cx, 8, sx12, g_Hst[1][p], g_X1, 1024, Wb1, b4 + 1, true);
        if (cx.kh == 0) epi_kh0(cx, L + 1, g_bsum + 4096, g_Cst + 65536,
                                g_Hst[1][p ^ 1], g_X2);
        else            epi_kh1(cx, L + 1);
        bar_arrive(tid, 1);                            // barrier 4t+1 -> gen b4+2

        gemm_kh(cx, 8, sx12, g_Hst[2][p], g_X2, 1024, Wb2, b4 + 2, true);
        if (cx.kh == 0) epi_kh0(cx, L + 2, g_bsum + 8192, g_Cst + 131072,
                                g_Hst[2][p ^ 1], g_Xfc);
        else            epi_kh1(cx, L + 2);
        bar_arrive(tid, 0);                            // barrier 4t+2 -> gen b4+3
        bar_wait(tid, b4 + 3);

        // fc: 256 CTAs tile 8(batch rows) x 32(col groups of 4)
        {
            int br = bc >> 5, cg2 = bc & 31;
            int o = tid >> 3, part = tid & 7;
            int b = br * 8 + (o >> 2);
            int dl = o & 3;
            int d = cg2 * 4 + dl;
            const float4* hp = (const float4*)(g_Xfc + b * 1024) + part * 16;
            const float4* wp = (const float4*)(sWfc + dl * 1024) + part * 16;
            float acc = 0.f;
#pragma unroll
            for (int k = 0; k < 16; ++k) {
                float4 hv = __ldcg(hp + k);
                float4 wv = wp[k];
                const __half2* h2 = (const __half2*)&hv;
                const __half2* w2 = (const __half2*)&wv;
#pragma unroll
                for (int j = 0; j < 4; ++j) {
                    float2 hf = __half22float2(h2[j]);
                    float2 wf = __half22float2(w2[j]);
                    acc = fmaf(hf.x, wf.x, acc);
                    acc = fmaf(hf.y, wf.y, acc);
                }
            }
            acc += __shfl_xor_sync(0xffffffff, acc, 1);
            acc += __shfl_xor_sync(0xffffffff, acc, 2);
            acc += __shfl_xor_sync(0xffffffff, acc, 4);
            if (part == 0) {
                float z = sigf(acc + bfc[d]);
                float v = (t + 1 < PLEN) ? x[(size_t)(t + 1) * 8192 + b * 128 + d] : z;
                out[(size_t)(t + 1) * 8192 + b * 128 + d] = v;
                g_In0[b * 128 + d] = __float2half(v);
            }
        }
        bar_arrive(tid, 1);                            // barrier 4t+3 -> gen b4+4
    }
}

// ---------------- launch (lstm_main is launch #4 for ncu) ----------------
extern "C" void kernel_launch(void* const* d_in, const int* in_sizes, int n_in,
                              void* d_out, int out_size) {
    const float* x    = (const float*)d_in[0];
    const float* h0   = (const float*)d_in[1];
    const float* c0   = (const float*)d_in[2];
    const float* Wih0 = (const float*)d_in[3];
    const float* Whh0 = (const float*)d_in[4];
    const float* bih0 = (const float*)d_in[5];
    const float* bhh0 = (const float*)d_in[6];
    const float* Wih1 = (const float*)d_in[7];
    const float* Whh1 = (const float*)d_in[8];
    const float* bih1 = (const float*)d_in[9];
    const float* bhh1 = (const float*)d_in[10];
    const float* Wih2 = (const float*)d_in[11];
    const float* Whh2 = (const float*)d_in[12];
    const float* bih2 = (const float*)d_in[13];
    const float* bhh2 = (const float*)d_in[14];
    const float* Wfc  = (const float*)d_in[15];
    const float* bfc  = (const float*)d_in[16];
    float* out = (float*)d_out;

    static bool attr_done = false;
    if (!attr_done) {
        cudaFuncSetAttribute(lstm_main, cudaFuncAttributeMaxDynamicSharedMemorySize,
                             SMEM_BYTES);
        attr_done = true;
    }

    int total = L0SZ + 2 * L12SZ;
    pack_all<<<(total + 255) / 256, 256>>>(Wih0, Whh0, Wih1, Whh1, Wih2, Whh2);
    pack_fc<<<512, 256>>>(Wfc);
    init_state<<<768, 256>>>(x, h0, c0, bih0, bhh0, bih1, bhh1, bih2, bhh2, out);
    lstm_main<<<NBLK, NTHR, SMEM_BYTES>>>(x, bfc, out);
}